// round 16
// baseline (speedup 1.0000x reference)
#include <cuda_runtime.h>
#include <cuda_fp16.h>
#include <cstdint>
#include <math_constants.h>

// Problem constants
#define BATCH 2
#define SEQ   2048
#define EMB   1024
#define HEADS 16
#define DHEAD 64
#define MTOT  (BATCH*SEQ)      // 4096
#define NORD  4

// ---------------- scratch (device globals; no cudaMalloc allowed) ------------
__device__ float g_opart[16 * MTOT * NORD];   // per-slice o partials

// fp16 q (split), k (single, accurate-rounded), v (split)
__device__ __align__(16) __half g_qh[MTOT * EMB];
__device__ __align__(16) __half g_ql[MTOT * EMB];
__device__ __align__(16) __half g_kh[MTOT * EMB];
__device__ __align__(16) __half g_vh[MTOT * EMB];
__device__ __align__(16) __half g_vl[MTOT * EMB];

// fp16 operands for projection GEMMs: x split (lo used for q,k only), W^T split
__device__ __align__(16) __half g_xh[MTOT * EMB];
__device__ __align__(16) __half g_xl[MTOT * EMB];
__device__ __align__(16) __half g_wthi[4 * EMB * EMB];  // W^T per weight, [n][k]
__device__ __align__(16) __half g_wtlo[4 * EMB * EMB];  // lo only used for z<2

// ======================= PTX helpers (arch-portable) =========================
__device__ __forceinline__ uint32_t smem_u32(const void* p) {
    uint32_t a;
    asm("{ .reg .u64 t; cvta.to.shared.u64 t, %1; cvt.u32.u64 %0, t; }"
        : "=r"(a) : "l"(p));
    return a;
}

#define CP_ASYNC16(dst, src) \
    asm volatile("cp.async.cg.shared.global [%0], [%1], 16;" :: "r"(dst), "l"(src))
#define CP_COMMIT() asm volatile("cp.async.commit_group;" ::: "memory")
#define CP_WAIT(n)  asm volatile("cp.async.wait_group %0;" :: "n"(n) : "memory")

__device__ __forceinline__ void ldsm_x4(uint32_t* r, uint32_t addr) {
    asm volatile("ldmatrix.sync.aligned.m8n8.x4.shared.b16 {%0,%1,%2,%3}, [%4];"
        : "=r"(r[0]), "=r"(r[1]), "=r"(r[2]), "=r"(r[3]) : "r"(addr));
}
__device__ __forceinline__ void ldsm_x4_t(uint32_t* r, uint32_t addr) {
    asm volatile("ldmatrix.sync.aligned.m8n8.x4.trans.shared.b16 {%0,%1,%2,%3}, [%4];"
        : "=r"(r[0]), "=r"(r[1]), "=r"(r[2]), "=r"(r[3]) : "r"(addr));
}

// D(f32) += A(f16) * B(f16), m16n8k16
__device__ __forceinline__ void mma16816h(float* c, const uint32_t* a, const uint32_t* b) {
    asm volatile(
        "mma.sync.aligned.m16n8k16.row.col.f32.f16.f16.f32 "
        "{%0,%1,%2,%3}, {%4,%5,%6,%7}, {%8,%9}, {%0,%1,%2,%3};"
        : "+f"(c[0]), "+f"(c[1]), "+f"(c[2]), "+f"(c[3])
        : "r"(a[0]), "r"(a[1]), "r"(a[2]), "r"(a[3]), "r"(b[0]), "r"(b[1]));
}

__device__ __forceinline__ uint32_t pack_h2(float a, float b) {
    __half2 h = __floats2half2_rn(a, b);
    return *reinterpret_cast<uint32_t*>(&h);
}

// ====================== prep kernels =========================================
// split x -> fp16 hi + lo
__global__ __launch_bounds__(256) void split_x_kernel(
    const float* __restrict__ x, __half* __restrict__ hi, __half* __restrict__ lo)
{
    const int i4 = blockIdx.x * blockDim.x + threadIdx.x;
    if (i4 >= MTOT * EMB / 4) return;
    float4 v = ((const float4*)x)[i4];
    __half h0 = __float2half_rn(v.x), h1 = __float2half_rn(v.y);
    __half h2 = __float2half_rn(v.z), h3 = __float2half_rn(v.w);
    uint2 rh, rl;
    __half2 p01 = __halves2half2(h0, h1), p23 = __halves2half2(h2, h3);
    rh.x = *reinterpret_cast<uint32_t*>(&p01);
    rh.y = *reinterpret_cast<uint32_t*>(&p23);
    rl.x = pack_h2(v.x - __half2float(h0), v.y - __half2float(h1));
    rl.y = pack_h2(v.z - __half2float(h2), v.w - __half2float(h3));
    *(uint2*)(hi + 4 * (size_t)i4) = rh;
    *(uint2*)(lo + 4 * (size_t)i4) = rl;
}

// transpose W [k][n] -> W^T [n][k] with fp16 hi/lo split, per-weight (blockIdx.z)
// lo written only for z<2 (q,k); v,h are 1-pass and never read it.
__global__ __launch_bounds__(256) void split_wt_kernel(
    const float* __restrict__ Wq, const float* __restrict__ Wk,
    const float* __restrict__ Wv, const float* __restrict__ Wo1,
    __half* __restrict__ wthi, __half* __restrict__ wtlo)
{
    const int z = blockIdx.z;
    const float* W = (z == 0) ? Wq : (z == 1) ? Wk : (z == 2) ? Wv : Wo1;
    __shared__ float ts[32][33];
    const int n0 = blockIdx.x * 32;
    const int k0 = blockIdx.y * 32;
    const int tx = threadIdx.x, ty = threadIdx.y;   // 32 x 8
#pragma unroll
    for (int i = 0; i < 4; i++)
        ts[ty + 8 * i][tx] = W[(size_t)(k0 + ty + 8 * i) * EMB + n0 + tx];
    __syncthreads();
    __half* oh = wthi + (size_t)z * EMB * EMB;
    __half* ol = wtlo + (size_t)z * EMB * EMB;
#pragma unroll
    for (int i = 0; i < 4; i++) {
        const int n = n0 + ty + 8 * i;
        float v = ts[tx][ty + 8 * i];          // = W[k0+tx][n]
        __half h = __float2half_rn(v);
        oh[(size_t)n * EMB + k0 + tx] = h;
        if (z < 2) {
            __half l = __float2half_rn(v - __half2float(h));
            ol[(size_t)n * EMB + k0 + tx] = l;
        }
    }
}

// =================== HMMA projection GEMM (fp16) =============================
// C[256x128] tile = X[256x1024] @ W[1024x128] + b.
// z in {0,1} (q,k): 3 passes (xh*Wh + xh*Wl + xl*Wh) -> accurate.
// z == 2   (v):     1 pass (xh*Wh), fp16 hi/lo output.
// z == 3   (h):     1 pass, fused order-weight head: relu(h) @ Wo2 partials
//                   written to g_opart (no g_h materialization).
// 8 warps, each 64x64. BK=32. 3-stage cp.async ring.
#define PROW 80                           // bytes per smem row (64 + 16 pad)
#define STAGE_BYTES (768 * PROW)          // 61440
#define PROJ_SMEM_BYTES (3 * STAGE_BYTES) // 184320

__global__ __launch_bounds__(256, 1) void proj_mma_kernel(
    const __half* __restrict__ xh, const __half* __restrict__ xl,
    const __half* __restrict__ wthi, const __half* __restrict__ wtlo,
    const float* __restrict__ bq, const float* __restrict__ bk,
    const float* __restrict__ bv, const float* __restrict__ bo1,
    const float* __restrict__ Wo2)
{
    extern __shared__ char smem[];
    const uint32_t sbase = smem_u32(smem);

    const int z = blockIdx.z;
    const bool split_ab = (z < 2);     // q,k: split A and split B (3 passes)
    const float* bias = (z == 0) ? bq : (z == 1) ? bk : (z == 2) ? bv : bo1;

    const int tid = threadIdx.x;
    const int wid = tid >> 5;
    const int lane = tid & 31;
    const int wr = wid >> 1;          // warp row (0..3): rows wr*64
    const int wc = wid & 1;           // warp col (0..1): cols wc*64
    const int m0 = blockIdx.y * 256;
    const int n0 = blockIdx.x * 128;

    const __half* A  = xh + (size_t)m0 * EMB;
    const __half* Al = xl + (size_t)m0 * EMB;
    const __half* Bh = wthi + (size_t)z * EMB * EMB + (size_t)n0 * EMB;
    const __half* Bl = wtlo + (size_t)z * EMB * EMB + (size_t)n0 * EMB;

    auto load_stage = [&](int s, int kc) {
        const uint32_t dbase = sbase + (uint32_t)s * STAGE_BYTES;
        const int r64 = tid >> 2;          // 0..63
        const int c16 = tid & 3;           // 16B column
#pragma unroll
        for (int t = 0; t < 12; t++) {
            const int grow = t * 64 + r64;        // smem row 0..767
            const __half* src;
            if (t < 4)       src = A  + (size_t)grow * EMB;
            else if (t < 8)  { if (!split_ab) continue;
                               src = Al + (size_t)(grow - 256) * EMB; }
            else if (t < 10) src = Bh + (size_t)(grow - 512) * EMB;
            else             { if (!split_ab) continue;
                               src = Bl + (size_t)(grow - 640) * EMB; }
            CP_ASYNC16(dbase + (uint32_t)grow * PROW + c16 * 16,
                       src + kc * 32 + c16 * 8);
        }
    };

    float acc[4][8][4];
#pragma unroll
    for (int mi = 0; mi < 4; mi++)
#pragma unroll
        for (int nj = 0; nj < 8; nj++)
#pragma unroll
            for (int e = 0; e < 4; e++) acc[mi][nj][e] = 0.0f;

    const int arow = lane & 15;
    const int ahalf = lane >> 4;
    const int brow = (lane & 7) + ((lane >> 4) << 3);
    const int bkoff = ((lane >> 3) & 1) * 16;

    load_stage(0, 0); CP_COMMIT();
    load_stage(1, 1); CP_COMMIT();

    const int NCH = EMB / 32;    // 32
    int s = 0, ps = 2;
    for (int kc = 0; kc < NCH; kc++) {
        if (kc + 1 < NCH) CP_WAIT(1); else CP_WAIT(0);
        __syncthreads();
        if (kc + 2 < NCH) {
            load_stage(ps, kc + 2);
            CP_COMMIT();
            if (++ps == 3) ps = 0;
        }

        const uint32_t st = sbase + (uint32_t)s * STAGE_BYTES;
        if (++s == 3) s = 0;
#pragma unroll
        for (int k16 = 0; k16 < 2; k16++) {
            uint32_t ah[4][4], al[4][4];
#pragma unroll
            for (int mi = 0; mi < 4; mi++) {
                const uint32_t ra = (uint32_t)(wr * 64 + mi * 16 + arow) * PROW
                                    + k16 * 32 + ahalf * 16;
                ldsm_x4(ah[mi], st + ra);
                if (split_ab) ldsm_x4(al[mi], st + 256 * PROW + ra);
            }
#pragma unroll
            for (int p = 0; p < 4; p++) {
                const uint32_t rb = (uint32_t)(wc * 64 + p * 16 + brow) * PROW
                                    + k16 * 32 + bkoff;
                uint32_t th[4], tl[4];
                ldsm_x4(th, st + 512 * PROW + rb);
                if (split_ab) ldsm_x4(tl, st + 640 * PROW + rb);
#pragma unroll
                for (int mi = 0; mi < 4; mi++) {
                    mma16816h(acc[mi][2 * p],     ah[mi], th);
                    mma16816h(acc[mi][2 * p + 1], ah[mi], th + 2);
                    if (split_ab) {
                        mma16816h(acc[mi][2 * p],     ah[mi], tl);
                        mma16816h(acc[mi][2 * p + 1], ah[mi], tl + 2);
                        mma16816h(acc[mi][2 * p],     al[mi], th);
                        mma16816h(acc[mi][2 * p + 1], al[mi], th + 2);
                    }
                }
            }
        }
    }

    // epilogue
    const int erow = lane >> 2;
    const int ecol = (lane & 3) * 2;
    float po[4][2][4];   // z==3: per-thread o partials [mi][rowhalf][4]
    if (z == 3) {
#pragma unroll
        for (int mi = 0; mi < 4; mi++)
#pragma unroll
            for (int hr2 = 0; hr2 < 2; hr2++)
#pragma unroll
                for (int c = 0; c < 4; c++) po[mi][hr2][c] = 0.0f;
    }
#pragma unroll
    for (int mi = 0; mi < 4; mi++) {
#pragma unroll
        for (int nj = 0; nj < 8; nj++) {
            const int row = m0 + wr * 64 + mi * 16 + erow;
            const int col = n0 + wc * 64 + nj * 8 + ecol;
            const float b0 = bias[col], b1 = bias[col + 1];
            float v00 = acc[mi][nj][0] + b0, v01 = acc[mi][nj][1] + b1;
            float v10 = acc[mi][nj][2] + b0, v11 = acc[mi][nj][3] + b1;
            const size_t o0 = (size_t)row * EMB + col;
            const size_t o1 = (size_t)(row + 8) * EMB + col;
            if (z == 3) {
                v00 = fmaxf(v00, 0.0f); v01 = fmaxf(v01, 0.0f);
                v10 = fmaxf(v10, 0.0f); v11 = fmaxf(v11, 0.0f);
                const float4 wa = *(const float4*)(Wo2 + (size_t)col * 4);
                const float4 wb = *(const float4*)(Wo2 + (size_t)(col + 1) * 4);
                po[mi][0][0] = fmaf(v00, wa.x, fmaf(v01, wb.x, po[mi][0][0]));
                po[mi][0][1] = fmaf(v00, wa.y, fmaf(v01, wb.y, po[mi][0][1]));
                po[mi][0][2] = fmaf(v00, wa.z, fmaf(v01, wb.z, po[mi][0][2]));
                po[mi][0][3] = fmaf(v00, wa.w, fmaf(v01, wb.w, po[mi][0][3]));
                po[mi][1][0] = fmaf(v10, wa.x, fmaf(v11, wb.x, po[mi][1][0]));
                po[mi][1][1] = fmaf(v10, wa.y, fmaf(v11, wb.y, po[mi][1][1]));
                po[mi][1][2] = fmaf(v10, wa.z, fmaf(v11, wb.z, po[mi][1][2]));
                po[mi][1][3] = fmaf(v10, wa.w, fmaf(v11, wb.w, po[mi][1][3]));
            } else if (z == 1) {
                *(uint32_t*)(g_kh + o0) = pack_h2(v00, v01);
                *(uint32_t*)(g_kh + o1) = pack_h2(v10, v11);
            } else {
                __half* Ch = (z == 0) ? g_qh : g_vh;
                __half* Cl = (z == 0) ? g_ql : g_vl;
                __half h00 = __float2half_rn(v00), h01 = __float2half_rn(v01);
                __half h10 = __float2half_rn(v10), h11 = __float2half_rn(v11);
                *(uint32_t*)(Ch + o0) = pack_h2(v00, v01);
                *(uint32_t*)(Ch + o1) = pack_h2(v10, v11);
                *(uint32_t*)(Cl + o0) =
                    pack_h2(v00 - __half2float(h00), v01 - __half2float(h01));
                *(uint32_t*)(Cl + o1) =
                    pack_h2(v10 - __half2float(h10), v11 - __half2float(h11));
            }
        }
    }
    if (z == 3) {
        // quad-reduce (over ecol lanes) then write slice = blockIdx.x*2 + wc
        const int sidx = blockIdx.x * 2 + wc;
        float* slice = g_opart + (size_t)sidx * MTOT * 4;
#pragma unroll
        for (int mi = 0; mi < 4; mi++) {
#pragma unroll
            for (int hr2 = 0; hr2 < 2; hr2++) {
                float c0 = po[mi][hr2][0], c1 = po[mi][hr2][1];
                float c2 = po[mi][hr2][2], c3 = po[mi][hr2][3];
#pragma unroll
                for (int mb = 1; mb < 4; mb <<= 1) {
                    c0 += __shfl_xor_sync(0xffffffffu, c0, mb);
                    c1 += __shfl_xor_sync(0xffffffffu, c1, mb);
                    c2 += __shfl_xor_sync(0xffffffffu, c2, mb);
                    c3 += __shfl_xor_sync(0xffffffffu, c3, mb);
                }
                if ((lane & 3) == 0) {
                    const int row = m0 + wr * 64 + mi * 16 + erow + hr2 * 8;
                    float4 r = { c0, c1, c2, c3 };
                    *(float4*)(slice + (size_t)row * 4) = r;
                }
            }
        }
    }
}

// =================== HMMA flash attention + fused mixing =====================
// CTA: 256 queries x 1 head. 8 warps; warp owns rows wid*32..+31 as two
// 16-row groups. 4-stage KV ring, one barrier per iteration.
// SOFTWARE-PIPELINED PV: iteration kt issues QK(kt) then PV(kt-1) (both
// independent of softmax(kt)) so the tensor queue holds ~264 MMAs while the
// softmax scalars execute -- hides the softmax phase behind the tensor pipe.
// Recurrence (O + PV(kt-1))*sc(kt) telescopes to the SAME FP op sequence as
// the original O*sc + PV. l rides the tensor pipe via ones-MMA.
#define ASTR 144
#define QROWS 256
#define QBUF (QROWS * ASTR)               // 36864
#define KVBUF (64 * ASTR)                 // 9216
#define ATT_STAGE (3 * KVBUF)             // Kh, Vh, Vl = 27648
#define OW_OFF (2 * QBUF + 4 * ATT_STAGE)               // 184320
#define ATT_SMEM_BYTES (OW_OFF + QROWS * 16)            // 188416

__global__ __launch_bounds__(256, 1) void attn_mma_kernel(
    const float* __restrict__ bo2, float* __restrict__ out)
{
    extern __shared__ char smem[];
    const uint32_t sb = smem_u32(smem);
    const uint32_t sQH = sb, sQL = sb + QBUF, sST = sb + 2 * QBUF;
    float4* sOW = (float4*)(smem + OW_OFF);

    const int qt = blockIdx.x;     // 0..7
    const int hd = blockIdx.y;
    const int b  = blockIdx.z;
    const int q0 = qt * QROWS;
    const int tid = threadIdx.x;
    const int wid = tid >> 5;
    const int lane = tid & 31;
    const size_t tok0 = (size_t)b * SEQ;
    const size_t hoff = (size_t)hd * DHEAD;

    const __half* Qh = g_qh + (tok0 + q0) * EMB + hoff;
    const __half* Ql = g_ql + (tok0 + q0) * EMB + hoff;
    const __half* Kh = g_kh + tok0 * EMB + hoff;
    const __half* Vh = g_vh + tok0 * EMB + hoff;
    const __half* Vl = g_vl + tok0 * EMB + hoff;

    // Q load (hi + lo, 256 rows), own commit group
#pragma unroll
    for (int t = 0; t < 16; t++) {
        const int idx = tid + t * 256;     // 0..4095
        const int arr = idx >> 11;
        const int w = idx & 2047;
        const int row = w >> 3;            // 0..255
        const int c = w & 7;
        const uint32_t dst = (arr ? sQL : sQH) + row * ASTR + c * 16;
        const void* src = (arr ? Ql : Qh) + (size_t)row * EMB + c * 8;
        CP_ASYNC16(dst, src);
    }
    CP_COMMIT();

    auto load_stage = [&](int s, int kt) {
        const int k0 = kt * 64;
        const __half* srcs[3] = { Kh, Vh, Vl };
        const uint32_t dbase = sST + (uint32_t)s * ATT_STAGE;
#pragma unroll
        for (int t = 0; t < 6; t++) {
            const int idx = tid + t * 256;   // 0..1535
            const int arr = idx >> 9;
            const int w = idx & 511;
            const int row = w >> 3;
            const int c = w & 7;
            const uint32_t dst = dbase + arr * KVBUF + row * ASTR + c * 16;
            const void* src = srcs[arr] + (size_t)(k0 + row) * EMB + c * 8;
            CP_ASYNC16(dst, src);
        }
    };

    load_stage(0, 0);
    CP_COMMIT();
    load_stage(1, 1);
    CP_COMMIT();

    // ---- order weights for this CTA's rows (overlaps the async fills) ----
    {
        const size_t grow = tok0 + q0 + tid;     // global row for thread tid
        float4 s4 = *(const float4*)bo2;
#pragma unroll
        for (int t = 0; t < 16; t++) {
            float4 p = ((const float4*)g_opart)[(size_t)t * MTOT + grow];
            s4.x += p.x; s4.y += p.y; s4.z += p.z; s4.w += p.w;
        }
        sOW[tid] = s4;
    }

    float mm[2][2];
    float oacc[2][8][4];
    float lacc[2][4];                      // l via ones-MMA: rows r / r+8
#pragma unroll
    for (int g = 0; g < 2; g++) {
        mm[g][0] = -CUDART_INF_F; mm[g][1] = -CUDART_INF_F;
#pragma unroll
        for (int e = 0; e < 4; e++) lacc[g][e] = 0.f;
#pragma unroll
        for (int nt = 0; nt < 8; nt++)
#pragma unroll
            for (int e = 0; e < 4; e++) oacc[g][nt][e] = 0.f;
    }
    const uint32_t ones_frag[2] = { 0x3C003C00u, 0x3C003C00u };  // half2(1,1)

    const uint32_t kbrow = (uint32_t)((lane & 7) + ((lane >> 4) << 3));
    const uint32_t kboff = (uint32_t)(((lane >> 3) & 1) << 4);
    const uint32_t vbrow = (uint32_t)((lane & 7) + (((lane >> 3) & 1) << 3));
    const uint32_t vboff = (uint32_t)((lane >> 4) << 4);
    const uint32_t qlrow = (uint32_t)(lane & 15);
    const uint32_t qhalf = (uint32_t)((lane >> 4) * 16);

    uint32_t ph[2][8][2];                  // P of the PREVIOUS tile

    // deferred-PV body (oacc/lacc += P(prev) V(prev) on stage stv)
    auto pv_block = [&](uint32_t stv) {
#pragma unroll
        for (int ks = 0; ks < 4; ks++) {
            uint32_t Ah0[4] = { ph[0][2 * ks][0], ph[0][2 * ks][1],
                                ph[0][2 * ks + 1][0], ph[0][2 * ks + 1][1] };
            uint32_t Ah1[4] = { ph[1][2 * ks][0], ph[1][2 * ks][1],
                                ph[1][2 * ks + 1][0], ph[1][2 * ks + 1][1] };
            mma16816h(lacc[0], Ah0, ones_frag);
            mma16816h(lacc[1], Ah1, ones_frag);
#pragma unroll
            for (int p = 0; p < 4; p++) {
                const uint32_t voff = (ks * 16 + vbrow) * ASTR + p * 32 + vboff;
                uint32_t th[4], tl[4];
                ldsm_x4_t(th, stv + 1 * KVBUF + voff);
                ldsm_x4_t(tl, stv + 2 * KVBUF + voff);
                mma16816h(oacc[0][2 * p],     Ah0, th);
                mma16816h(oacc[0][2 * p + 1], Ah0, th + 2);
                mma16816h(oacc[0][2 * p],     Ah0, tl);
                mma16816h(oacc[0][2 * p + 1], Ah0, tl + 2);
                mma16816h(oacc[1][2 * p],     Ah1, th);
                mma16816h(oacc[1][2 * p + 1], Ah1, th + 2);
                mma16816h(oacc[1][2 * p],     Ah1, tl);
                mma16816h(oacc[1][2 * p + 1], Ah1, tl + 2);
            }
        }
    };

    const int NT = SEQ / 64;   // 32
    for (int kt = 0; kt < NT; kt++) {
        if (kt + 1 < NT) CP_WAIT(1); else CP_WAIT(0);
        __syncthreads();                 // one barrier per iteration
        if (kt + 2 < NT) {
            load_stage((kt + 2) & 3, kt + 2);
            CP_COMMIT();
        }

        const uint32_t st  = sST + (uint32_t)(kt & 3) * ATT_STAGE;
        const uint32_t stv = sST + (uint32_t)((kt - 1) & 3) * ATT_STAGE;

        // ---- QK(kt) : S = (Qh+Ql) Kh^T, 2 passes, 2 row-groups ----
        float sacc[2][8][4];
#pragma unroll
        for (int g = 0; g < 2; g++)
#pragma unroll
            for (int nt = 0; nt < 8; nt++)
#pragma unroll
                for (int e = 0; e < 4; e++) sacc[g][nt][e] = 0.f;

#pragma unroll
        for (int ks = 0; ks < 4; ks++) {
            uint32_t qh[2][4], ql[2][4];
#pragma unroll
            for (int g = 0; g < 2; g++) {
                const uint32_t off = (uint32_t)(wid * 32 + g * 16 + qlrow) * ASTR
                                     + ks * 32 + qhalf;
                ldsm_x4(qh[g], sQH + off);
                ldsm_x4(ql[g], sQL + off);
            }
#pragma unroll
            for (int p = 0; p < 4; p++) {
                const uint32_t boff = (p * 16 + kbrow) * ASTR + ks * 32 + kboff;
                uint32_t th[4];
                ldsm_x4(th, st + boff);
#pragma unroll
                for (int g = 0; g < 2; g++) {
                    mma16816h(sacc[g][2 * p],     qh[g], th);
                    mma16816h(sacc[g][2 * p + 1], qh[g], th + 2);
                    mma16816h(sacc[g][2 * p],     ql[g], th);
                    mma16816h(sacc[g][2 * p + 1], ql[g], th + 2);
                }
            }
        }

        // ---- PV(kt-1): independent of sacc -> fills tensor queue while
        //      the softmax below stalls on the sacc scoreboard ----
        if (kt > 0) pv_block(stv);

        // ---- softmax(kt): writes ph for NEXT iteration's PV ----
#pragma unroll
        for (int g = 0; g < 2; g++) {
            float tmax0 = -CUDART_INF_F, tmax1 = -CUDART_INF_F;
#pragma unroll
            for (int nt = 0; nt < 8; nt++) {
                tmax0 = fmaxf(tmax0, fmaxf(sacc[g][nt][0], sacc[g][nt][1]));
                tmax1 = fmaxf(tmax1, fmaxf(sacc[g][nt][2], sacc[g][nt][3]));
            }
#pragma unroll
            for (int m = 1; m < 4; m <<= 1) {
                tmax0 = fmaxf(tmax0, __shfl_xor_sync(0xffffffffu, tmax0, m));
                tmax1 = fmaxf(tmax1, __shfl_xor_sync(0xffffffffu, tmax1, m));
            }
            const float mnew0 = fmaxf(mm[g][0], tmax0);
            const float mnew1 = fmaxf(mm[g][1], tmax1);
            const float sc0 = __expf(mm[g][0] - mnew0);
            const float sc1 = __expf(mm[g][1] - mnew1);

#pragma unroll
            for (int nt = 0; nt < 8; nt++) {
                float p00 = __expf(sacc[g][nt][0] - mnew0);
                float p01 = __expf(sacc[g][nt][1] - mnew0);
                float p10 = __expf(sacc[g][nt][2] - mnew1);
                float p11 = __expf(sacc[g][nt][3] - mnew1);
                ph[g][nt][0] = pack_h2(p00, p01);
                ph[g][nt][1] = pack_h2(p10, p11);
            }
            mm[g][0] = mnew0;
            mm[g][1] = mnew1;
            // rescale AFTER the deferred PV has been accumulated
            lacc[g][0] *= sc0; lacc[g][1] *= sc0;
            lacc[g][2] *= sc1; lacc[g][3] *= sc1;
#pragma unroll
            for (int nt = 0; nt < 8; nt++) {
                oacc[g][nt][0] *= sc0; oacc[g][nt][1] *= sc0;
                oacc[g][nt][2] *= sc1; oacc[g][nt][3] *= sc1;
            }
        }
    }

    // ---- drain: PV of the final tile ----
    pv_block(sST + (uint32_t)((NT - 1) & 3) * ATT_STAGE);

    // ---- fused epilogue: org = O/l, then polynomial mixing -> out ----
#pragma unroll
    for (int g = 0; g < 2; g++) {
        const float inv0 = 1.0f / lacc[g][0];
        const float inv1 = 1.0f / lacc[g][2];
        const int r0 = q0 + wid * 32 + g * 16 + (lane >> 2);
        const int r1 = r0 + 8;
        const float4 w0v = sOW[r0 - q0];
        const float4 w1v = sOW[r1 - q0];
#pragma unroll
        for (int nt = 0; nt < 8; nt++) {
            const int col = (int)hoff + nt * 8 + (lane & 3) * 2;
            float g00 = oacc[g][nt][0] * inv0, g01 = oacc[g][nt][1] * inv0;
            float g10 = oacc[g][nt][2] * inv1, g11 = oacc[g][nt][3] * inv1;
            float2 o0, o1;
            o0.x = g00 * fmaf(g00, fmaf(g00, fmaf(g00, w0v.w, w0v.z), w0v.y), w0v.x);
            o0.y = g01 * fmaf(g01, fmaf(g01, fmaf(g01, w0v.w, w0v.z), w0v.y), w0v.x);
            o1.x = g10 * fmaf(g10, fmaf(g10, fmaf(g10, w1v.w, w1v.z), w1v.y), w1v.x);
            o1.y = g11 * fmaf(g11, fmaf(g11, fmaf(g11, w1v.w, w1v.z), w1v.y), w1v.x);
            *(float2*)(out + (tok0 + r0) * EMB + col) = o0;
            *(float2*)(out + (tok0 + r1) * EMB + col) = o1;
        }
    }
}

// ------------------------------ launch -------------------------------------
extern "C" void kernel_launch(void* const* d_in, const int* in_sizes, int n_in,
                              void* d_out, int out_size)
{
    const float* x   = (const float*)d_in[0];
    const float* Wq  = (const float*)d_in[1];
    const float* bq  = (const float*)d_in[2];
    const float* Wk  = (const float*)d_in[3];
    const float* bk  = (const float*)d_in[4];
    const float* Wv  = (const float*)d_in[5];
    const float* bv  = (const float*)d_in[6];
    const float* Wo1 = (const float*)d_in[7];
    const float* bo1 = (const float*)d_in[8];
    const float* Wo2 = (const float*)d_in[9];
    const float* bo2 = (const float*)d_in[10];
    float* out = (float*)d_out;

    __half *xh, *xl, *wthi, *wtlo;
    cudaGetSymbolAddress((void**)&xh, g_xh);
    cudaGetSymbolAddress((void**)&xl, g_xl);
    cudaGetSymbolAddress((void**)&wthi, g_wthi);
    cudaGetSymbolAddress((void**)&wtlo, g_wtlo);

    cudaFuncSetAttribute(proj_mma_kernel,
                         cudaFuncAttributeMaxDynamicSharedMemorySize, PROJ_SMEM_BYTES);
    cudaFuncSetAttribute(attn_mma_kernel,
                         cudaFuncAttributeMaxDynamicSharedMemorySize, ATT_SMEM_BYTES);

    // 1) split x into fp16 hi/lo; split W^T into fp16 hi/lo (lo for q,k only)
    const int nv4 = MTOT * EMB / 4;
    split_x_kernel<<<(nv4 + 255) / 256, 256>>>(x, xh, xl);
    split_wt_kernel<<<dim3(EMB / 32, EMB / 32, 4), dim3(32, 8)>>>(
        Wq, Wk, Wv, Wo1, wthi, wtlo);

    // 2) HMMA projections: q,k 3-pass; v 1-pass; h 1-pass w/ fused owt partials
    proj_mma_kernel<<<dim3(EMB / 128, MTOT / 256, 4), 256, PROJ_SMEM_BYTES>>>(
        xh, xl, wthi, wtlo, bq, bk, bv, bo1, Wo2);

    // 3) HMMA flash attention (software-pipelined PV, 4-stage ring)
    //    + in-kernel o reduction + fused polynomial mixing -> out
    attn_mma_kernel<<<dim3(SEQ / QROWS, HEADS, BATCH), 256, ATT_SMEM_BYTES>>>(bo2, out);
}

// round 17
// speedup vs baseline: 1.0366x; 1.0366x over previous
#include <cuda_runtime.h>
#include <cuda_fp16.h>
#include <cstdint>
#include <math_constants.h>

// Problem constants
#define BATCH 2
#define SEQ   2048
#define EMB   1024
#define HEADS 16
#define DHEAD 64
#define MTOT  (BATCH*SEQ)      // 4096
#define NORD  4

// ---------------- scratch (device globals; no cudaMalloc allowed) ------------
__device__ float g_opart[16 * MTOT * NORD];   // per-slice o partials

// fp16 q (split), k (single, accurate-rounded), v (split)
__device__ __align__(16) __half g_qh[MTOT * EMB];
__device__ __align__(16) __half g_ql[MTOT * EMB];
__device__ __align__(16) __half g_kh[MTOT * EMB];
__device__ __align__(16) __half g_vh[MTOT * EMB];
__device__ __align__(16) __half g_vl[MTOT * EMB];

// fp16 operands for projection GEMMs: x split (lo used for q,k only), W^T split
__device__ __align__(16) __half g_xh[MTOT * EMB];
__device__ __align__(16) __half g_xl[MTOT * EMB];
__device__ __align__(16) __half g_wthi[4 * EMB * EMB];  // W^T per weight, [n][k]
__device__ __align__(16) __half g_wtlo[4 * EMB * EMB];  // lo only used for z<2

// ======================= PTX helpers (arch-portable) =========================
__device__ __forceinline__ uint32_t smem_u32(const void* p) {
    uint32_t a;
    asm("{ .reg .u64 t; cvta.to.shared.u64 t, %1; cvt.u32.u64 %0, t; }"
        : "=r"(a) : "l"(p));
    return a;
}

#define CP_ASYNC16(dst, src) \
    asm volatile("cp.async.cg.shared.global [%0], [%1], 16;" :: "r"(dst), "l"(src))
#define CP_COMMIT() asm volatile("cp.async.commit_group;" ::: "memory")
#define CP_WAIT(n)  asm volatile("cp.async.wait_group %0;" :: "n"(n) : "memory")

__device__ __forceinline__ void ldsm_x4(uint32_t* r, uint32_t addr) {
    asm volatile("ldmatrix.sync.aligned.m8n8.x4.shared.b16 {%0,%1,%2,%3}, [%4];"
        : "=r"(r[0]), "=r"(r[1]), "=r"(r[2]), "=r"(r[3]) : "r"(addr));
}
__device__ __forceinline__ void ldsm_x4_t(uint32_t* r, uint32_t addr) {
    asm volatile("ldmatrix.sync.aligned.m8n8.x4.trans.shared.b16 {%0,%1,%2,%3}, [%4];"
        : "=r"(r[0]), "=r"(r[1]), "=r"(r[2]), "=r"(r[3]) : "r"(addr));
}

// D(f32) += A(f16) * B(f16), m16n8k16
__device__ __forceinline__ void mma16816h(float* c, const uint32_t* a, const uint32_t* b) {
    asm volatile(
        "mma.sync.aligned.m16n8k16.row.col.f32.f16.f16.f32 "
        "{%0,%1,%2,%3}, {%4,%5,%6,%7}, {%8,%9}, {%0,%1,%2,%3};"
        : "+f"(c[0]), "+f"(c[1]), "+f"(c[2]), "+f"(c[3])
        : "r"(a[0]), "r"(a[1]), "r"(a[2]), "r"(a[3]), "r"(b[0]), "r"(b[1]));
}

__device__ __forceinline__ uint32_t pack_h2(float a, float b) {
    __half2 h = __floats2half2_rn(a, b);
    return *reinterpret_cast<uint32_t*>(&h);
}

// ====================== prep kernels =========================================
// split x -> fp16 hi + lo
__global__ __launch_bounds__(256) void split_x_kernel(
    const float* __restrict__ x, __half* __restrict__ hi, __half* __restrict__ lo)
{
    const int i4 = blockIdx.x * blockDim.x + threadIdx.x;
    if (i4 >= MTOT * EMB / 4) return;
    float4 v = ((const float4*)x)[i4];
    __half h0 = __float2half_rn(v.x), h1 = __float2half_rn(v.y);
    __half h2 = __float2half_rn(v.z), h3 = __float2half_rn(v.w);
    uint2 rh, rl;
    __half2 p01 = __halves2half2(h0, h1), p23 = __halves2half2(h2, h3);
    rh.x = *reinterpret_cast<uint32_t*>(&p01);
    rh.y = *reinterpret_cast<uint32_t*>(&p23);
    rl.x = pack_h2(v.x - __half2float(h0), v.y - __half2float(h1));
    rl.y = pack_h2(v.z - __half2float(h2), v.w - __half2float(h3));
    *(uint2*)(hi + 4 * (size_t)i4) = rh;
    *(uint2*)(lo + 4 * (size_t)i4) = rl;
}

// transpose W [k][n] -> W^T [n][k] with fp16 hi/lo split, per-weight (blockIdx.z)
// lo written only for z<2 (q,k); v,h are 1-pass and never read it.
__global__ __launch_bounds__(256) void split_wt_kernel(
    const float* __restrict__ Wq, const float* __restrict__ Wk,
    const float* __restrict__ Wv, const float* __restrict__ Wo1,
    __half* __restrict__ wthi, __half* __restrict__ wtlo)
{
    const int z = blockIdx.z;
    const float* W = (z == 0) ? Wq : (z == 1) ? Wk : (z == 2) ? Wv : Wo1;
    __shared__ float ts[32][33];
    const int n0 = blockIdx.x * 32;
    const int k0 = blockIdx.y * 32;
    const int tx = threadIdx.x, ty = threadIdx.y;   // 32 x 8
#pragma unroll
    for (int i = 0; i < 4; i++)
        ts[ty + 8 * i][tx] = W[(size_t)(k0 + ty + 8 * i) * EMB + n0 + tx];
    __syncthreads();
    __half* oh = wthi + (size_t)z * EMB * EMB;
    __half* ol = wtlo + (size_t)z * EMB * EMB;
#pragma unroll
    for (int i = 0; i < 4; i++) {
        const int n = n0 + ty + 8 * i;
        float v = ts[tx][ty + 8 * i];          // = W[k0+tx][n]
        __half h = __float2half_rn(v);
        oh[(size_t)n * EMB + k0 + tx] = h;
        if (z < 2) {
            __half l = __float2half_rn(v - __half2float(h));
            ol[(size_t)n * EMB + k0 + tx] = l;
        }
    }
}

// =================== HMMA projection GEMM (fp16) =============================
// C[256x128] tile = X[256x1024] @ W[1024x128] + b.
// z in {0,1} (q,k): 3 passes (xh*Wh + xh*Wl + xl*Wh) -> accurate.
// z == 2   (v):     1 pass (xh*Wh), fp16 hi/lo output.
// z == 3   (h):     1 pass, fused order-weight head: relu(h) @ Wo2 partials
//                   written to g_opart (no g_h materialization).
// 8 warps, each 64x64. BK=32. 3-stage cp.async ring.
#define PROW 80                           // bytes per smem row (64 + 16 pad)
#define STAGE_BYTES (768 * PROW)          // 61440
#define PROJ_SMEM_BYTES (3 * STAGE_BYTES) // 184320

__global__ __launch_bounds__(256, 1) void proj_mma_kernel(
    const __half* __restrict__ xh, const __half* __restrict__ xl,
    const __half* __restrict__ wthi, const __half* __restrict__ wtlo,
    const float* __restrict__ bq, const float* __restrict__ bk,
    const float* __restrict__ bv, const float* __restrict__ bo1,
    const float* __restrict__ Wo2)
{
    extern __shared__ char smem[];
    const uint32_t sbase = smem_u32(smem);

    const int z = blockIdx.z;
    const bool split_ab = (z < 2);     // q,k: split A and split B (3 passes)
    const float* bias = (z == 0) ? bq : (z == 1) ? bk : (z == 2) ? bv : bo1;

    const int tid = threadIdx.x;
    const int wid = tid >> 5;
    const int lane = tid & 31;
    const int wr = wid >> 1;          // warp row (0..3): rows wr*64
    const int wc = wid & 1;           // warp col (0..1): cols wc*64
    const int m0 = blockIdx.y * 256;
    const int n0 = blockIdx.x * 128;

    const __half* A  = xh + (size_t)m0 * EMB;
    const __half* Al = xl + (size_t)m0 * EMB;
    const __half* Bh = wthi + (size_t)z * EMB * EMB + (size_t)n0 * EMB;
    const __half* Bl = wtlo + (size_t)z * EMB * EMB + (size_t)n0 * EMB;

    auto load_stage = [&](int s, int kc) {
        const uint32_t dbase = sbase + (uint32_t)s * STAGE_BYTES;
        const int r64 = tid >> 2;          // 0..63
        const int c16 = tid & 3;           // 16B column
#pragma unroll
        for (int t = 0; t < 12; t++) {
            const int grow = t * 64 + r64;        // smem row 0..767
            const __half* src;
            if (t < 4)       src = A  + (size_t)grow * EMB;
            else if (t < 8)  { if (!split_ab) continue;
                               src = Al + (size_t)(grow - 256) * EMB; }
            else if (t < 10) src = Bh + (size_t)(grow - 512) * EMB;
            else             { if (!split_ab) continue;
                               src = Bl + (size_t)(grow - 640) * EMB; }
            CP_ASYNC16(dbase + (uint32_t)grow * PROW + c16 * 16,
                       src + kc * 32 + c16 * 8);
        }
    };

    float acc[4][8][4];
#pragma unroll
    for (int mi = 0; mi < 4; mi++)
#pragma unroll
        for (int nj = 0; nj < 8; nj++)
#pragma unroll
            for (int e = 0; e < 4; e++) acc[mi][nj][e] = 0.0f;

    const int arow = lane & 15;
    const int ahalf = lane >> 4;
    const int brow = (lane & 7) + ((lane >> 4) << 3);
    const int bkoff = ((lane >> 3) & 1) * 16;

    load_stage(0, 0); CP_COMMIT();
    load_stage(1, 1); CP_COMMIT();

    const int NCH = EMB / 32;    // 32
    int s = 0, ps = 2;
    for (int kc = 0; kc < NCH; kc++) {
        if (kc + 1 < NCH) CP_WAIT(1); else CP_WAIT(0);
        __syncthreads();
        if (kc + 2 < NCH) {
            load_stage(ps, kc + 2);
            CP_COMMIT();
            if (++ps == 3) ps = 0;
        }

        const uint32_t st = sbase + (uint32_t)s * STAGE_BYTES;
        if (++s == 3) s = 0;
#pragma unroll
        for (int k16 = 0; k16 < 2; k16++) {
            uint32_t ah[4][4], al[4][4];
#pragma unroll
            for (int mi = 0; mi < 4; mi++) {
                const uint32_t ra = (uint32_t)(wr * 64 + mi * 16 + arow) * PROW
                                    + k16 * 32 + ahalf * 16;
                ldsm_x4(ah[mi], st + ra);
                if (split_ab) ldsm_x4(al[mi], st + 256 * PROW + ra);
            }
#pragma unroll
            for (int p = 0; p < 4; p++) {
                const uint32_t rb = (uint32_t)(wc * 64 + p * 16 + brow) * PROW
                                    + k16 * 32 + bkoff;
                uint32_t th[4], tl[4];
                ldsm_x4(th, st + 512 * PROW + rb);
                if (split_ab) ldsm_x4(tl, st + 640 * PROW + rb);
#pragma unroll
                for (int mi = 0; mi < 4; mi++) {
                    mma16816h(acc[mi][2 * p],     ah[mi], th);
                    mma16816h(acc[mi][2 * p + 1], ah[mi], th + 2);
                    if (split_ab) {
                        mma16816h(acc[mi][2 * p],     ah[mi], tl);
                        mma16816h(acc[mi][2 * p + 1], ah[mi], tl + 2);
                        mma16816h(acc[mi][2 * p],     al[mi], th);
                        mma16816h(acc[mi][2 * p + 1], al[mi], th + 2);
                    }
                }
            }
        }
    }

    // epilogue
    const int erow = lane >> 2;
    const int ecol = (lane & 3) * 2;
    float po[4][2][4];   // z==3: per-thread o partials [mi][rowhalf][4]
    if (z == 3) {
#pragma unroll
        for (int mi = 0; mi < 4; mi++)
#pragma unroll
            for (int hr2 = 0; hr2 < 2; hr2++)
#pragma unroll
                for (int c = 0; c < 4; c++) po[mi][hr2][c] = 0.0f;
    }
#pragma unroll
    for (int mi = 0; mi < 4; mi++) {
#pragma unroll
        for (int nj = 0; nj < 8; nj++) {
            const int row = m0 + wr * 64 + mi * 16 + erow;
            const int col = n0 + wc * 64 + nj * 8 + ecol;
            const float b0 = bias[col], b1 = bias[col + 1];
            float v00 = acc[mi][nj][0] + b0, v01 = acc[mi][nj][1] + b1;
            float v10 = acc[mi][nj][2] + b0, v11 = acc[mi][nj][3] + b1;
            const size_t o0 = (size_t)row * EMB + col;
            const size_t o1 = (size_t)(row + 8) * EMB + col;
            if (z == 3) {
                v00 = fmaxf(v00, 0.0f); v01 = fmaxf(v01, 0.0f);
                v10 = fmaxf(v10, 0.0f); v11 = fmaxf(v11, 0.0f);
                const float4 wa = *(const float4*)(Wo2 + (size_t)col * 4);
                const float4 wb = *(const float4*)(Wo2 + (size_t)(col + 1) * 4);
                po[mi][0][0] = fmaf(v00, wa.x, fmaf(v01, wb.x, po[mi][0][0]));
                po[mi][0][1] = fmaf(v00, wa.y, fmaf(v01, wb.y, po[mi][0][1]));
                po[mi][0][2] = fmaf(v00, wa.z, fmaf(v01, wb.z, po[mi][0][2]));
                po[mi][0][3] = fmaf(v00, wa.w, fmaf(v01, wb.w, po[mi][0][3]));
                po[mi][1][0] = fmaf(v10, wa.x, fmaf(v11, wb.x, po[mi][1][0]));
                po[mi][1][1] = fmaf(v10, wa.y, fmaf(v11, wb.y, po[mi][1][1]));
                po[mi][1][2] = fmaf(v10, wa.z, fmaf(v11, wb.z, po[mi][1][2]));
                po[mi][1][3] = fmaf(v10, wa.w, fmaf(v11, wb.w, po[mi][1][3]));
            } else if (z == 1) {
                *(uint32_t*)(g_kh + o0) = pack_h2(v00, v01);
                *(uint32_t*)(g_kh + o1) = pack_h2(v10, v11);
            } else {
                __half* Ch = (z == 0) ? g_qh : g_vh;
                __half* Cl = (z == 0) ? g_ql : g_vl;
                __half h00 = __float2half_rn(v00), h01 = __float2half_rn(v01);
                __half h10 = __float2half_rn(v10), h11 = __float2half_rn(v11);
                *(uint32_t*)(Ch + o0) = pack_h2(v00, v01);
                *(uint32_t*)(Ch + o1) = pack_h2(v10, v11);
                *(uint32_t*)(Cl + o0) =
                    pack_h2(v00 - __half2float(h00), v01 - __half2float(h01));
                *(uint32_t*)(Cl + o1) =
                    pack_h2(v10 - __half2float(h10), v11 - __half2float(h11));
            }
        }
    }
    if (z == 3) {
        // quad-reduce (over ecol lanes) then write slice = blockIdx.x*2 + wc
        const int sidx = blockIdx.x * 2 + wc;
        float* slice = g_opart + (size_t)sidx * MTOT * 4;
#pragma unroll
        for (int mi = 0; mi < 4; mi++) {
#pragma unroll
            for (int hr2 = 0; hr2 < 2; hr2++) {
                float c0 = po[mi][hr2][0], c1 = po[mi][hr2][1];
                float c2 = po[mi][hr2][2], c3 = po[mi][hr2][3];
#pragma unroll
                for (int mb = 1; mb < 4; mb <<= 1) {
                    c0 += __shfl_xor_sync(0xffffffffu, c0, mb);
                    c1 += __shfl_xor_sync(0xffffffffu, c1, mb);
                    c2 += __shfl_xor_sync(0xffffffffu, c2, mb);
                    c3 += __shfl_xor_sync(0xffffffffu, c3, mb);
                }
                if ((lane & 3) == 0) {
                    const int row = m0 + wr * 64 + mi * 16 + erow + hr2 * 8;
                    float4 r = { c0, c1, c2, c3 };
                    *(float4*)(slice + (size_t)row * 4) = r;
                }
            }
        }
    }
}

// =================== HMMA flash attention + fused mixing =====================
// CTA: 256 queries x 1 head. 8 warps; warp owns rows wid*32..+31 as two
// 16-row groups. 3-stage KV ring, one barrier per iteration.
// Per-iteration order: QK(both groups) -> softmax(g0) -> PV(g0) ->
// softmax(g1) -> PV(g1). PV(g0)'s ~134 tensor MMAs drain while softmax(g1)'s
// scalars execute, hiding ~half the scalar block without extending register
// live ranges (R16's full deferral grew regs 214->236 and regressed).
// l rides the tensor pipe via ones-MMA.
#define ASTR 144
#define QROWS 256
#define QBUF (QROWS * ASTR)               // 36864
#define KVBUF (64 * ASTR)                 // 9216
#define ATT_STAGE (3 * KVBUF)             // Kh, Vh, Vl = 27648
#define OW_OFF (2 * QBUF + 3 * ATT_STAGE)               // 156672
#define ATT_SMEM_BYTES (OW_OFF + QROWS * 16)            // 160768

__global__ __launch_bounds__(256, 1) void attn_mma_kernel(
    const float* __restrict__ bo2, float* __restrict__ out)
{
    extern __shared__ char smem[];
    const uint32_t sb = smem_u32(smem);
    const uint32_t sQH = sb, sQL = sb + QBUF, sST = sb + 2 * QBUF;
    float4* sOW = (float4*)(smem + OW_OFF);

    const int qt = blockIdx.x;     // 0..7
    const int hd = blockIdx.y;
    const int b  = blockIdx.z;
    const int q0 = qt * QROWS;
    const int tid = threadIdx.x;
    const int wid = tid >> 5;
    const int lane = tid & 31;
    const size_t tok0 = (size_t)b * SEQ;
    const size_t hoff = (size_t)hd * DHEAD;

    const __half* Qh = g_qh + (tok0 + q0) * EMB + hoff;
    const __half* Ql = g_ql + (tok0 + q0) * EMB + hoff;
    const __half* Kh = g_kh + tok0 * EMB + hoff;
    const __half* Vh = g_vh + tok0 * EMB + hoff;
    const __half* Vl = g_vl + tok0 * EMB + hoff;

    // Q load (hi + lo, 256 rows), own commit group
#pragma unroll
    for (int t = 0; t < 16; t++) {
        const int idx = tid + t * 256;     // 0..4095
        const int arr = idx >> 11;
        const int w = idx & 2047;
        const int row = w >> 3;            // 0..255
        const int c = w & 7;
        const uint32_t dst = (arr ? sQL : sQH) + row * ASTR + c * 16;
        const void* src = (arr ? Ql : Qh) + (size_t)row * EMB + c * 8;
        CP_ASYNC16(dst, src);
    }
    CP_COMMIT();

    auto load_stage = [&](int s, int kt) {
        const int k0 = kt * 64;
        const __half* srcs[3] = { Kh, Vh, Vl };
        const uint32_t dbase = sST + (uint32_t)s * ATT_STAGE;
#pragma unroll
        for (int t = 0; t < 6; t++) {
            const int idx = tid + t * 256;   // 0..1535
            const int arr = idx >> 9;
            const int w = idx & 511;
            const int row = w >> 3;
            const int c = w & 7;
            const uint32_t dst = dbase + arr * KVBUF + row * ASTR + c * 16;
            const void* src = srcs[arr] + (size_t)(k0 + row) * EMB + c * 8;
            CP_ASYNC16(dst, src);
        }
    };

    load_stage(0, 0);
    CP_COMMIT();
    load_stage(1, 1);
    CP_COMMIT();

    // ---- order weights for this CTA's rows (overlaps the async fills) ----
    {
        const size_t grow = tok0 + q0 + tid;     // global row for thread tid
        float4 s4 = *(const float4*)bo2;
#pragma unroll
        for (int t = 0; t < 16; t++) {
            float4 p = ((const float4*)g_opart)[(size_t)t * MTOT + grow];
            s4.x += p.x; s4.y += p.y; s4.z += p.z; s4.w += p.w;
        }
        sOW[tid] = s4;
    }

    float mm[2][2];
    float oacc[2][8][4];
    float lacc[2][4];                      // l via ones-MMA: rows r / r+8
#pragma unroll
    for (int g = 0; g < 2; g++) {
        mm[g][0] = -CUDART_INF_F; mm[g][1] = -CUDART_INF_F;
#pragma unroll
        for (int e = 0; e < 4; e++) lacc[g][e] = 0.f;
#pragma unroll
        for (int nt = 0; nt < 8; nt++)
#pragma unroll
            for (int e = 0; e < 4; e++) oacc[g][nt][e] = 0.f;
    }
    const uint32_t ones_frag[2] = { 0x3C003C00u, 0x3C003C00u };  // half2(1,1)

    const uint32_t kbrow = (uint32_t)((lane & 7) + ((lane >> 4) << 3));
    const uint32_t kboff = (uint32_t)(((lane >> 3) & 1) << 4);
    const uint32_t vbrow = (uint32_t)((lane & 7) + (((lane >> 3) & 1) << 3));
    const uint32_t vboff = (uint32_t)((lane >> 4) << 4);
    const uint32_t qlrow = (uint32_t)(lane & 15);
    const uint32_t qhalf = (uint32_t)((lane >> 4) * 16);

    const int NT = SEQ / 64;   // 32
    int s = 0, ps = 2;
    for (int kt = 0; kt < NT; kt++) {
        if (kt + 1 < NT) CP_WAIT(1); else CP_WAIT(0);
        __syncthreads();                 // the ONLY barrier per iteration
        if (kt + 2 < NT) {
            load_stage(ps, kt + 2);
            CP_COMMIT();
            if (++ps == 3) ps = 0;
        }

        const uint32_t st = sST + (uint32_t)s * ATT_STAGE;
        if (++s == 3) s = 0;

        // ---- S = (Qh+Ql) Kh^T : 2 passes, 2 row-groups ----
        float sacc[2][8][4];
#pragma unroll
        for (int g = 0; g < 2; g++)
#pragma unroll
            for (int nt = 0; nt < 8; nt++)
#pragma unroll
                for (int e = 0; e < 4; e++) sacc[g][nt][e] = 0.f;

#pragma unroll
        for (int ks = 0; ks < 4; ks++) {
            uint32_t qh[2][4], ql[2][4];
#pragma unroll
            for (int g = 0; g < 2; g++) {
                const uint32_t off = (uint32_t)(wid * 32 + g * 16 + qlrow) * ASTR
                                     + ks * 32 + qhalf;
                ldsm_x4(qh[g], sQH + off);
                ldsm_x4(ql[g], sQL + off);
            }
#pragma unroll
            for (int p = 0; p < 4; p++) {
                const uint32_t boff = (p * 16 + kbrow) * ASTR + ks * 32 + kboff;
                uint32_t th[4];
                ldsm_x4(th, st + boff);
#pragma unroll
                for (int g = 0; g < 2; g++) {
                    mma16816h(sacc[g][2 * p],     qh[g], th);
                    mma16816h(sacc[g][2 * p + 1], qh[g], th + 2);
                    mma16816h(sacc[g][2 * p],     ql[g], th);
                    mma16816h(sacc[g][2 * p + 1], ql[g], th + 2);
                }
            }
        }

        // ---- per group: softmax(g) then PV(g); PV(g0) tensor work drains
        //      while softmax(g1) scalars execute ----
#pragma unroll
        for (int g = 0; g < 2; g++) {
            float tmax0 = -CUDART_INF_F, tmax1 = -CUDART_INF_F;
#pragma unroll
            for (int nt = 0; nt < 8; nt++) {
                tmax0 = fmaxf(tmax0, fmaxf(sacc[g][nt][0], sacc[g][nt][1]));
                tmax1 = fmaxf(tmax1, fmaxf(sacc[g][nt][2], sacc[g][nt][3]));
            }
#pragma unroll
            for (int m = 1; m < 4; m <<= 1) {
                tmax0 = fmaxf(tmax0, __shfl_xor_sync(0xffffffffu, tmax0, m));
                tmax1 = fmaxf(tmax1, __shfl_xor_sync(0xffffffffu, tmax1, m));
            }
            const float mnew0 = fmaxf(mm[g][0], tmax0);
            const float mnew1 = fmaxf(mm[g][1], tmax1);
            const float sc0 = __expf(mm[g][0] - mnew0);
            const float sc1 = __expf(mm[g][1] - mnew1);

            uint32_t ph[8][2];
#pragma unroll
            for (int nt = 0; nt < 8; nt++) {
                float p00 = __expf(sacc[g][nt][0] - mnew0);
                float p01 = __expf(sacc[g][nt][1] - mnew0);
                float p10 = __expf(sacc[g][nt][2] - mnew1);
                float p11 = __expf(sacc[g][nt][3] - mnew1);
                ph[nt][0] = pack_h2(p00, p01);
                ph[nt][1] = pack_h2(p10, p11);
            }
            mm[g][0] = mnew0;
            mm[g][1] = mnew1;
            lacc[g][0] *= sc0; lacc[g][1] *= sc0;
            lacc[g][2] *= sc1; lacc[g][3] *= sc1;
#pragma unroll
            for (int nt = 0; nt < 8; nt++) {
                oacc[g][nt][0] *= sc0; oacc[g][nt][1] *= sc0;
                oacc[g][nt][2] *= sc1; oacc[g][nt][3] *= sc1;
            }

            // ---- PV(g): O[g] += P (Vh+Vl), l[g] += P @ ones ----
#pragma unroll
            for (int ks = 0; ks < 4; ks++) {
                uint32_t Ah_[4] = { ph[2 * ks][0], ph[2 * ks][1],
                                    ph[2 * ks + 1][0], ph[2 * ks + 1][1] };
                mma16816h(lacc[g], Ah_, ones_frag);
#pragma unroll
                for (int p = 0; p < 4; p++) {
                    const uint32_t voff = (ks * 16 + vbrow) * ASTR + p * 32 + vboff;
                    uint32_t th[4], tl[4];
                    ldsm_x4_t(th, st + 1 * KVBUF + voff);
                    ldsm_x4_t(tl, st + 2 * KVBUF + voff);
                    mma16816h(oacc[g][2 * p],     Ah_, th);
                    mma16816h(oacc[g][2 * p + 1], Ah_, th + 2);
                    mma16816h(oacc[g][2 * p],     Ah_, tl);
                    mma16816h(oacc[g][2 * p + 1], Ah_, tl + 2);
                }
            }
        }
        // no trailing barrier: 3-stage ring + next iteration's pre-compute
        // barrier protect stage reuse
    }

    // ---- fused epilogue: org = O/l, then polynomial mixing -> out ----
#pragma unroll
    for (int g = 0; g < 2; g++) {
        const float inv0 = 1.0f / lacc[g][0];
        const float inv1 = 1.0f / lacc[g][2];
        const int r0 = q0 + wid * 32 + g * 16 + (lane >> 2);
        const int r1 = r0 + 8;
        const float4 w0v = sOW[r0 - q0];
        const float4 w1v = sOW[r1 - q0];
#pragma unroll
        for (int nt = 0; nt < 8; nt++) {
            const int col = (int)hoff + nt * 8 + (lane & 3) * 2;
            float g00 = oacc[g][nt][0] * inv0, g01 = oacc[g][nt][1] * inv0;
            float g10 = oacc[g][nt][2] * inv1, g11 = oacc[g][nt][3] * inv1;
            float2 o0, o1;
            o0.x = g00 * fmaf(g00, fmaf(g00, fmaf(g00, w0v.w, w0v.z), w0v.y), w0v.x);
            o0.y = g01 * fmaf(g01, fmaf(g01, fmaf(g01, w0v.w, w0v.z), w0v.y), w0v.x);
            o1.x = g10 * fmaf(g10, fmaf(g10, fmaf(g10, w1v.w, w1v.z), w1v.y), w1v.x);
            o1.y = g11 * fmaf(g11, fmaf(g11, fmaf(g11, w1v.w, w1v.z), w1v.y), w1v.x);
            *(float2*)(out + (tok0 + r0) * EMB + col) = o0;
            *(float2*)(out + (tok0 + r1) * EMB + col) = o1;
        }
    }
}

// ------------------------------ launch -------------------------------------
extern "C" void kernel_launch(void* const* d_in, const int* in_sizes, int n_in,
                              void* d_out, int out_size)
{
    const float* x   = (const float*)d_in[0];
    const float* Wq  = (const float*)d_in[1];
    const float* bq  = (const float*)d_in[2];
    const float* Wk  = (const float*)d_in[3];
    const float* bk  = (const float*)d_in[4];
    const float* Wv  = (const float*)d_in[5];
    const float* bv  = (const float*)d_in[6];
    const float* Wo1 = (const float*)d_in[7];
    const float* bo1 = (const float*)d_in[8];
    const float* Wo2 = (const float*)d_in[9];
    const float* bo2 = (const float*)d_in[10];
    float* out = (float*)d_out;

    __half *xh, *xl, *wthi, *wtlo;
    cudaGetSymbolAddress((void**)&xh, g_xh);
    cudaGetSymbolAddress((void**)&xl, g_xl);
    cudaGetSymbolAddress((void**)&wthi, g_wthi);
    cudaGetSymbolAddress((void**)&wtlo, g_wtlo);

    cudaFuncSetAttribute(proj_mma_kernel,
                         cudaFuncAttributeMaxDynamicSharedMemorySize, PROJ_SMEM_BYTES);
    cudaFuncSetAttribute(attn_mma_kernel,
                         cudaFuncAttributeMaxDynamicSharedMemorySize, ATT_SMEM_BYTES);

    // 1) split x into fp16 hi/lo; split W^T into fp16 hi/lo (lo for q,k only)
    const int nv4 = MTOT * EMB / 4;
    split_x_kernel<<<(nv4 + 255) / 256, 256>>>(x, xh, xl);
    split_wt_kernel<<<dim3(EMB / 32, EMB / 32, 4), dim3(32, 8)>>>(
        Wq, Wk, Wv, Wo1, wthi, wtlo);

    // 2) HMMA projections: q,k 3-pass; v 1-pass; h 1-pass w/ fused owt partials
    proj_mma_kernel<<<dim3(EMB / 128, MTOT / 256, 4), 256, PROJ_SMEM_BYTES>>>(
        xh, xl, wthi, wtlo, bq, bk, bv, bo1, Wo2);

    // 3) HMMA flash attention (per-group softmax/PV interleave, 3-stage ring)
    //    + in-kernel o reduction + fused polynomial mixing -> out
    attn_mma_kernel<<<dim3(SEQ / QROWS, HEADS, BATCH), 256, ATT_SMEM_BYTES>>>(bo2, out);
}